// round 2
// baseline (speedup 1.0000x reference)
#include <cuda_runtime.h>
#include <cstdint>

typedef unsigned long long ull;

#define D_IN   4096
#define R_RANK 16
#define O_OUT  4096
#define M_TOT  8192
#define SCALE  2.0f      // alpha/rank = 32/16
#define DC1    256       // d-chunk for A staging in kernel 1
#define TOK2   32        // tokens per CTA in kernel 2

// Intermediate h = s * x @ A^T, stored as packed f32 r-pairs: [m][8] x ull
__device__ ull g_h[M_TOT * (R_RANK / 2)];

// ---- packed f32x2 helpers (ptxas will not auto-fuse these from C++) ----
__device__ __forceinline__ ull pack2(float a, float b) {
    ull r; asm("mov.b64 %0, {%1, %2};" : "=l"(r) : "f"(a), "f"(b)); return r;
}
__device__ __forceinline__ void unpack2(ull v, float &a, float &b) {
    asm("mov.b64 {%0, %1}, %2;" : "=f"(a), "=f"(b) : "l"(v));
}
__device__ __forceinline__ ull fma2(ull a, ull b, ull c) {
    ull d; asm("fma.rn.f32x2 %0, %1, %2, %3;" : "=l"(d) : "l"(a), "l"(b), "l"(c)); return d;
}
__device__ __forceinline__ ull add2(ull a, ull b) {
    ull d; asm("add.rn.f32x2 %0, %1, %2;" : "=l"(d) : "l"(a), "l"(b)); return d;
}
__device__ __forceinline__ ull mul2(ull a, ull b) {
    ull d; asm("mul.rn.f32x2 %0, %1, %2;" : "=l"(d) : "l"(a), "l"(b)); return d;
}

// ===================== kernel 1: h = SCALE * (x @ A^T) =====================
// 128 threads (4 warps), each warp owns 4 tokens -> 16 tokens/CTA, grid 512.
// A^T chunk staged in smem in 4d-blocks: offset(d,r) = (d/4)*68 + (d%4)*16 + r.
// Block stride 68 floats => lane's LDS.128 reads are conflict-free per 8-lane
// phase. x read as float4 per lane (perfectly coalesced).
__global__ void __launch_bounds__(128, 4)
lora_p1(const float* __restrict__ x, const float* __restrict__ A) {
    __shared__ float sA[(DC1 / 4) * 68];   // 64 blocks * 68 = 4352 floats = 17 KB

    const int tid  = threadIdx.x;
    const int lane = tid & 31;
    const int warp = tid >> 5;
    const int m0   = blockIdx.x * 16 + warp * 4;

    ull acc[32];                            // [t*8 + p] packed r-pair partials
    #pragma unroll
    for (int i = 0; i < 32; ++i) acc[i] = 0ull;

    const float* x0 = x + (size_t)m0 * D_IN;
    const float* x1 = x0 + D_IN;
    const float* x2 = x1 + D_IN;
    const float* x3 = x2 + D_IN;

    for (int dc = 0; dc < D_IN; dc += DC1) {
        // Stage A chunk: 4096 floats, 32 per thread. Global reads coalesced
        // (consecutive dl per warp); smem stores at most 2-way conflicted.
        #pragma unroll
        for (int i = 0; i < (DC1 * R_RANK) / 128; ++i) {   // 32 iters
            int idx = tid + i * 128;
            int r   = idx >> 8;            // idx / DC1
            int dl  = idx & (DC1 - 1);
            sA[(dl >> 2) * 68 + (dl & 3) * 16 + r] = A[r * D_IN + dc + dl];
        }
        __syncthreads();

        #pragma unroll
        for (int j = 0; j < DC1 / 128; ++j) {              // 2 iters
            int blk = j * 32 + lane;                       // 4d-block index
            int d   = dc + blk * 4;
            float4 v0 = *(const float4*)(x0 + d);
            float4 v1 = *(const float4*)(x1 + d);
            float4 v2 = *(const float4*)(x2 + d);
            float4 v3 = *(const float4*)(x3 + d);
            float xs0[4] = {v0.x, v0.y, v0.z, v0.w};
            float xs1[4] = {v1.x, v1.y, v1.z, v1.w};
            float xs2[4] = {v2.x, v2.y, v2.z, v2.w};
            float xs3[4] = {v3.x, v3.y, v3.z, v3.w};
            const float* ab = sA + blk * 68;

            #pragma unroll
            for (int dd = 0; dd < 4; ++dd) {
                const ulonglong2* ap = (const ulonglong2*)(ab + dd * 16);
                ulonglong2 q0 = ap[0], q1 = ap[1], q2 = ap[2], q3 = ap[3];
                ull a2[8] = {q0.x, q0.y, q1.x, q1.y, q2.x, q2.y, q3.x, q3.y};
                ull w0 = pack2(xs0[dd], xs0[dd]);
                ull w1 = pack2(xs1[dd], xs1[dd]);
                ull w2 = pack2(xs2[dd], xs2[dd]);
                ull w3 = pack2(xs3[dd], xs3[dd]);
                #pragma unroll
                for (int p = 0; p < 8; ++p) {
                    acc[p]      = fma2(w0, a2[p], acc[p]);
                    acc[8 + p]  = fma2(w1, a2[p], acc[8 + p]);
                    acc[16 + p] = fma2(w2, a2[p], acc[16 + p]);
                    acc[24 + p] = fma2(w3, a2[p], acc[24 + p]);
                }
            }
        }
        __syncthreads();
    }

    // Recursive-halving butterfly: 31 packed exchanges instead of a full
    // all-to-all. Lane L ends holding acc[0] = full d-sum of original index L
    // (token t = L>>3, r-pair p = L&7).
    #pragma unroll
    for (int k = 16; k >= 1; k >>= 1) {
        const bool hi = (lane & k) != 0;
        #pragma unroll
        for (int i = 0; i < k; ++i) {
            ull send = hi ? acc[i] : acc[i + k];
            ull got  = __shfl_xor_sync(0xffffffffu, send, k);
            ull keep = hi ? acc[i + k] : acc[i];
            acc[i] = add2(keep, got);
        }
    }

    ull res = mul2(acc[0], pack2(SCALE, SCALE));
    int t  = lane >> 3;
    int rp = lane & 7;
    g_h[(size_t)(m0 + t) * 8 + rp] = res;   // warp stores 256B contiguous
}

// ===================== kernel 2: out = h @ B^T =====================
// Lane owns 4 consecutive o-columns; its 64 B-values live in registers and
// are reused across every token (zero B re-traffic). h broadcast per token
// (L1 hit). Warp covers 128 consecutive o -> STG.128 fully coalesced.
// grid = (M_TOT/TOK2, O_OUT/512) = (256, 8) CTAs of 128 threads.
__global__ void __launch_bounds__(128, 4)
lora_p2(const float* __restrict__ B, float* __restrict__ out) {
    const int lane = threadIdx.x & 31;
    const int warp = threadIdx.x >> 5;
    const int o0   = blockIdx.y * 512 + warp * 128 + lane * 4;

    ull b2[4][8];                           // 4 o-rows x 8 packed r-pairs
    #pragma unroll
    for (int oo = 0; oo < 4; ++oo) {
        const ulonglong2* bp = (const ulonglong2*)(B + (size_t)(o0 + oo) * R_RANK);
        ulonglong2 q0 = bp[0], q1 = bp[1], q2 = bp[2], q3 = bp[3];
        b2[oo][0] = q0.x; b2[oo][1] = q0.y; b2[oo][2] = q1.x; b2[oo][3] = q1.y;
        b2[oo][4] = q2.x; b2[oo][5] = q2.y; b2[oo][6] = q3.x; b2[oo][7] = q3.y;
    }

    const int m0 = blockIdx.x * TOK2;
    #pragma unroll 2
    for (int t = 0; t < TOK2; ++t) {
        int m = m0 + t;
        const ulonglong2* hp = (const ulonglong2*)(g_h + (size_t)m * 8);
        ulonglong2 u0 = hp[0], u1 = hp[1], u2 = hp[2], u3 = hp[3];
        ull h2[8] = {u0.x, u0.y, u1.x, u1.y, u2.x, u2.y, u3.x, u3.y};

        ull s0 = 0ull, s1 = 0ull, s2 = 0ull, s3 = 0ull;
        #pragma unroll
        for (int p = 0; p < 8; ++p) {
            s0 = fma2(h2[p], b2[0][p], s0);
            s1 = fma2(h2[p], b2[1][p], s1);
            s2 = fma2(h2[p], b2[2][p], s2);
            s3 = fma2(h2[p], b2[3][p], s3);
        }
        float a, b, c, d, e, f, g, h;
        unpack2(s0, a, b); unpack2(s1, c, d);
        unpack2(s2, e, f); unpack2(s3, g, h);
        float4 r4 = make_float4(a + b, c + d, e + f, g + h);
        *(float4*)(out + (size_t)m * O_OUT + o0) = r4;
    }
}

extern "C" void kernel_launch(void* const* d_in, const int* in_sizes, int n_in,
                              void* d_out, int out_size) {
    const float* x = (const float*)d_in[0];
    const float* A = (const float*)d_in[1];   // [16, 4096]
    const float* B = (const float*)d_in[2];   // [4096, 16]
    float* out = (float*)d_out;

    lora_p1<<<M_TOT / 16, 128>>>(x, A);
    dim3 g2(M_TOT / TOK2, O_OUT / 512);       // (256, 8)
    lora_p2<<<g2, 128>>>(B, out);
}

// round 7
// speedup vs baseline: 1.2239x; 1.2239x over previous
#include <cuda_runtime.h>
#include <cstdint>

typedef unsigned long long ull;

#define D_IN   4096
#define R_RANK 16
#define O_OUT  4096
#define M_TOT  8192
#define SCALE  2.0f          // alpha/rank = 32/16
#define DC1    256           // d-chunk per pipeline stage in p1
#define NSTAGE (D_IN / DC1)  // 16
#define TOK2   64            // tokens per CTA in p2

// ---- device scratch (no allocs allowed) ----
// h = s * x @ A^T, packed f32 r-pairs: [m][8] ull
__device__ __align__(16) ull g_h[M_TOT * 8];
// A pre-transposed into blocked layout: block(d/4) stride 68 floats,
// offset(d,r) = (d>>2)*68 + (d&3)*16 + r.  (4096/4)*68 floats.
__device__ __align__(16) float g_At[(D_IN / 4) * 68];

// ---- packed f32x2 helpers ----
__device__ __forceinline__ ull pack2(float a, float b) {
    ull r; asm("mov.b64 %0, {%1, %2};" : "=l"(r) : "f"(a), "f"(b)); return r;
}
__device__ __forceinline__ void unpack2(ull v, float &a, float &b) {
    asm("mov.b64 {%0, %1}, %2;" : "=f"(a), "=f"(b) : "l"(v));
}
__device__ __forceinline__ ull fma2(ull a, ull b, ull c) {
    ull d; asm("fma.rn.f32x2 %0, %1, %2, %3;" : "=l"(d) : "l"(a), "l"(b), "l"(c)); return d;
}
__device__ __forceinline__ ull add2(ull a, ull b) {
    ull d; asm("add.rn.f32x2 %0, %1, %2;" : "=l"(d) : "l"(a), "l"(b)); return d;
}
__device__ __forceinline__ ull mul2(ull a, ull b) {
    ull d; asm("mul.rn.f32x2 %0, %1, %2;" : "=l"(d) : "l"(a), "l"(b)); return d;
}

// ---- async-copy / mbarrier helpers ----
__device__ __forceinline__ uint32_t smem_u32(const void* p) {
    uint32_t a;
    asm("{ .reg .u64 t; cvta.to.shared.u64 t, %1; cvt.u32.u64 %0, t; }"
        : "=r"(a) : "l"(p));
    return a;
}
__device__ __forceinline__ void mbar_init(uint32_t m, uint32_t cnt) {
    asm volatile("mbarrier.init.shared.b64 [%0], %1;" :: "r"(m), "r"(cnt) : "memory");
}
__device__ __forceinline__ void mbar_expect_tx(uint32_t m, uint32_t bytes) {
    asm volatile("mbarrier.arrive.expect_tx.shared.b64 _, [%0], %1;"
                 :: "r"(m), "r"(bytes) : "memory");
}
__device__ __forceinline__ void mbar_wait(uint32_t m, uint32_t parity) {
    asm volatile(
        "{\n\t.reg .pred P;\n"
        "WL_%=:\n\t"
        "mbarrier.try_wait.parity.acquire.cta.shared::cta.b64 P, [%0], %1, 0x989680;\n\t"
        "@!P bra WL_%=;\n\t}"
        :: "r"(m), "r"(parity) : "memory");
}
__device__ __forceinline__ void bulk_g2s(uint32_t dst, const void* src,
                                         uint32_t bytes, uint32_t mbar) {
    asm volatile(
        "cp.async.bulk.shared::cta.global.mbarrier::complete_tx::bytes "
        "[%0], [%1], %2, [%3];"
        :: "r"(dst), "l"(src), "r"(bytes), "r"(mbar) : "memory");
}

// ===================== kernel 0: pre-transpose A =====================
__global__ void lora_p0(const float* __restrict__ A) {
    int idx = blockIdx.x * 256 + threadIdx.x;   // coalesced over A
    int r = idx >> 12;
    int d = idx & (D_IN - 1);
    g_At[(d >> 2) * 68 + (d & 3) * 16 + r] = A[idx];
}

// ===================== kernel 1: h = SCALE * (x @ A^T) =====================
// 128 threads (4 warps x 4 tokens = 16 tokens/CTA), grid 512.
// Double-buffered cp.async.bulk pipeline stages x tiles (16x1KB rows) and
// pre-transposed A slabs (17408B contiguous) into smem.
#define X_BUF_B  (16 * DC1 * 4)          // 16384
#define A_BUF_B  ((DC1 / 4) * 68 * 4)    // 17408
#define STAGE_B  (X_BUF_B + A_BUF_B)     // per-stage tx bytes
#define SM_X(b)  ((b) * X_BUF_B)
#define SM_A(b)  (2 * X_BUF_B + (b) * A_BUF_B)
#define SM_BAR   (2 * X_BUF_B + 2 * A_BUF_B)
#define SM_TOTAL (SM_BAR + 16)

__global__ void __launch_bounds__(128, 3)
lora_p1(const float* __restrict__ x) {
    extern __shared__ __align__(16) char smem[];
    const uint32_t sbase = smem_u32(smem);

    const int tid  = threadIdx.x;
    const int lane = tid & 31;
    const int warp = tid >> 5;
    const int ctaM = blockIdx.x * 16;
    const int m0   = ctaM + warp * 4;

    if (tid == 0) { mbar_init(sbase + SM_BAR, 1); mbar_init(sbase + SM_BAR + 8, 1); }
    __syncthreads();

    // prologue: issue stages 0 and 1
    if (tid == 0) {
        #pragma unroll
        for (int s = 0; s < 2; ++s) {
            uint32_t bar = sbase + SM_BAR + s * 8;
            mbar_expect_tx(bar, STAGE_B);
            #pragma unroll
            for (int t = 0; t < 16; ++t)
                bulk_g2s(sbase + SM_X(s) + t * (DC1 * 4),
                         x + (size_t)(ctaM + t) * D_IN + s * DC1,
                         DC1 * 4, bar);
            bulk_g2s(sbase + SM_A(s), (const char*)g_At + s * A_BUF_B,
                     A_BUF_B, bar);
        }
    }

    ull acc[32];
    #pragma unroll
    for (int i = 0; i < 32; ++i) acc[i] = 0ull;

    for (int s = 0; s < NSTAGE; ++s) {
        const int b = s & 1;
        mbar_wait(sbase + SM_BAR + b * 8, (s >> 1) & 1);

        const float4* xb = (const float4*)(smem + SM_X(b));   // [16][DC1/4]
        const float*  ab = (const float*)(smem + SM_A(b));

        #pragma unroll
        for (int j = 0; j < DC1 / 128; ++j) {                 // 2 iters
            int blk = j * 32 + lane;
            float4 v0 = xb[(warp * 4 + 0) * (DC1 / 4) + blk];
            float4 v1 = xb[(warp * 4 + 1) * (DC1 / 4) + blk];
            float4 v2 = xb[(warp * 4 + 2) * (DC1 / 4) + blk];
            float4 v3 = xb[(warp * 4 + 3) * (DC1 / 4) + blk];
            float xs0[4] = {v0.x, v0.y, v0.z, v0.w};
            float xs1[4] = {v1.x, v1.y, v1.z, v1.w};
            float xs2[4] = {v2.x, v2.y, v2.z, v2.w};
            float xs3[4] = {v3.x, v3.y, v3.z, v3.w};
            const float* abk = ab + blk * 68;

            #pragma unroll
            for (int dd = 0; dd < 4; ++dd) {
                const ulonglong2* ap = (const ulonglong2*)(abk + dd * 16);
                ulonglong2 q0 = ap[0], q1 = ap[1], q2 = ap[2], q3 = ap[3];
                ull a2[8] = {q0.x, q0.y, q1.x, q1.y, q2.x, q2.y, q3.x, q3.y};
                ull w0 = pack2(xs0[dd], xs0[dd]);
                ull w1 = pack2(xs1[dd], xs1[dd]);
                ull w2 = pack2(xs2[dd], xs2[dd]);
                ull w3 = pack2(xs3[dd], xs3[dd]);
                #pragma unroll
                for (int p = 0; p < 8; ++p) {
                    acc[p]      = fma2(w0, a2[p], acc[p]);
                    acc[8 + p]  = fma2(w1, a2[p], acc[8 + p]);
                    acc[16 + p] = fma2(w2, a2[p], acc[16 + p]);
                    acc[24 + p] = fma2(w3, a2[p], acc[24 + p]);
                }
            }
        }
        __syncthreads();   // all lanes done with buffer b

        if (tid == 0 && s + 2 < NSTAGE) {
            const int ns = s + 2;
            uint32_t bar = sbase + SM_BAR + b * 8;
            mbar_expect_tx(bar, STAGE_B);
            #pragma unroll
            for (int t = 0; t < 16; ++t)
                bulk_g2s(sbase + SM_X(b) + t * (DC1 * 4),
                         x + (size_t)(ctaM + t) * D_IN + ns * DC1,
                         DC1 * 4, bar);
            bulk_g2s(sbase + SM_A(b), (const char*)g_At + ns * A_BUF_B,
                     A_BUF_B, bar);
        }
    }

    // Recursive-halving packed butterfly: lane L ends with d-sum of index L
    // (token t = L>>3, r-pair p = L&7).
    #pragma unroll
    for (int k = 16; k >= 1; k >>= 1) {
        const bool hi = (lane & k) != 0;
        #pragma unroll
        for (int i = 0; i < k; ++i) {
            ull send = hi ? acc[i] : acc[i + k];
            ull got  = __shfl_xor_sync(0xffffffffu, send, k);
            ull keep = hi ? acc[i + k] : acc[i];
            acc[i] = add2(keep, got);
        }
    }
    ull res = mul2(acc[0], pack2(SCALE, SCALE));
    g_h[(size_t)(m0 + (lane >> 3)) * 8 + (lane & 7)] = res;
}

// ===================== kernel 2: out = h @ B^T =====================
// 128 threads; lane owns 2 consecutive o (32 B-regs); h for 64 tokens staged
// in smem once; token loop unrolled x2. grid = (M/64, O/256) = (128, 16).
__global__ void __launch_bounds__(128, 5)
lora_p2(const float* __restrict__ B, float* __restrict__ out) {
    __shared__ __align__(16) ull sh[TOK2 * 8];   // 4 KB

    const int tid  = threadIdx.x;
    const int lane = tid & 31;
    const int warp = tid >> 5;
    const int o0   = blockIdx.y * 256 + warp * 64 + lane * 2;
    const int m0   = blockIdx.x * TOK2;

    // B rows for this lane's 2 outputs -> registers (reused for all tokens)
    ull b2[2][8];
    #pragma unroll
    for (int oo = 0; oo < 2; ++oo) {
        const ulonglong2* bp = (const ulonglong2*)(B + (size_t)(o0 + oo) * R_RANK);
        ulonglong2 q0 = bp[0], q1 = bp[1], q2 = bp[2], q3 = bp[3];
        b2[oo][0] = q0.x; b2[oo][1] = q0.y; b2[oo][2] = q1.x; b2[oo][3] = q1.y;
        b2[oo][4] = q2.x; b2[oo][5] = q2.y; b2[oo][6] = q3.x; b2[oo][7] = q3.y;
    }

    // Stage this CTA's h slice (coalesced, 2 LDG.128/thread)
    {
        const ulonglong2* src = (const ulonglong2*)(g_h + (size_t)m0 * 8);
        ulonglong2* dst = (ulonglong2*)sh;
        dst[tid]       = src[tid];
        dst[tid + 128] = src[tid + 128];
    }
    __syncthreads();

    #pragma unroll 4
    for (int t = 0; t < TOK2; t += 2) {
        const ulonglong2* hp0 = (const ulonglong2*)(sh + (t + 0) * 8);
        const ulonglong2* hp1 = (const ulonglong2*)(sh + (t + 1) * 8);
        ulonglong2 u0 = hp0[0], u1 = hp0[1], u2 = hp0[2], u3 = hp0[3];
        ulonglong2 w0 = hp1[0], w1 = hp1[1], w2 = hp1[2], w3 = hp1[3];
        ull ha[8] = {u0.x, u0.y, u1.x, u1.y, u2.x, u2.y, u3.x, u3.y};
        ull hb[8] = {w0.x, w0.y, w1.x, w1.y, w2.x, w2.y, w3.x, w3.y};

        ull s00 = 0ull, s01 = 0ull, s10 = 0ull, s11 = 0ull;
        #pragma unroll
        for (int p = 0; p < 8; ++p) {
            s00 = fma2(ha[p], b2[0][p], s00);
            s01 = fma2(ha[p], b2[1][p], s01);
            s10 = fma2(hb[p], b2[0][p], s10);
            s11 = fma2(hb[p], b2[1][p], s11);
        }
        float a, b, c, d;
        unpack2(s00, a, b); unpack2(s01, c, d);
        *(float2*)(out + (size_t)(m0 + t) * O_OUT + o0) = make_float2(a + b, c + d);
        unpack2(s10, a, b); unpack2(s11, c, d);
        *(float2*)(out + (size_t)(m0 + t + 1) * O_OUT + o0) = make_float2(a + b, c + d);
    }
}

extern "C" void kernel_launch(void* const* d_in, const int* in_sizes, int n_in,
                              void* d_out, int out_size) {
    const float* x = (const float*)d_in[0];
    const float* A = (const float*)d_in[1];   // [16, 4096]
    const float* B = (const float*)d_in[2];   // [4096, 16]
    float* out = (float*)d_out;

    cudaFuncSetAttribute(lora_p1, cudaFuncAttributeMaxDynamicSharedMemorySize,
                         SM_TOTAL);

    lora_p0<<<(R_RANK * D_IN) / 256, 256>>>(A);
    lora_p1<<<M_TOT / 16, 128, SM_TOTAL>>>(x);
    dim3 g2(M_TOT / TOK2, O_OUT / 256);       // (128, 16)
    lora_p2<<<g2, 128>>>(B, out);
}